// round 13
// baseline (speedup 1.0000x reference)
#include <cuda_runtime.h>
#include <cuda_fp16.h>

#define FN   262144
#define FNC  4096
#define FD   5
#define FK   4
#define W_JAC (2.0f/3.0f)

// ---- static device scratch (zero-initialized; kernels restore zeros) -------
__device__ __half g_Ach[FNC * FNC];    // fp16 RAP accumulator / coarse operator (32 MB)
__device__ float  g_dc[FNC];           // fp32 diagonal accumulator
__device__ float  g_wdc[FNC];          // W / diag(Ac)
__device__ float  g_bc[FNC];           // zero on entry (re-zeroed by prolong)
__device__ float  g_xc[2 * FNC];
__device__ float  g_xbuf[2 * FN];

// ---- RAP: one thread per (row i, nz j); 16 fp16 atomics + fp32 diag --------
__global__ void k_rap(const float* __restrict__ Av, const int* __restrict__ Acl,
                      const float* __restrict__ Pv, const int* __restrict__ Pc) {
    int t = blockIdx.x * blockDim.x + threadIdx.x;
    if (t >= FN * FD) return;
    int i = t / FD;
    int j = t - i * FD;
    int cj = __ldg(&Acl[i * FD + j]);
    float a = __ldg(&Av[i * FD + j]);
    float4 pa4 = __ldg((const float4*)(Pv + i * 4));
    int4   ia4 = __ldg((const int4*)(Pc + i * 4));
    float4 qb4 = __ldg((const float4*)(Pv + cj * 4));
    int4   ib4 = __ldg((const int4*)(Pc + cj * 4));
    float pa[FK] = {pa4.x * a, pa4.y * a, pa4.z * a, pa4.w * a};
    int   ia[FK] = {ia4.x, ia4.y, ia4.z, ia4.w};
    float qb[FK] = {qb4.x, qb4.y, qb4.z, qb4.w};
    int   ib[FK] = {ib4.x, ib4.y, ib4.z, ib4.w};
#pragma unroll
    for (int ka = 0; ka < FK; ka++) {
        int base = ia[ka] * FNC;
#pragma unroll
        for (int kb = 0; kb < FK; kb++) {
            float v = pa[ka] * qb[kb];
            atomicAdd(&g_Ach[base + ib[kb]], __float2half(v));
            if (ia[ka] == ib[kb])
                atomicAdd(&g_dc[ia[ka]], v);   // accurate fp32 diagonal
        }
    }
}

// ---- fine smoother (R1 AoS form): xout = xin + W*(b - A xin)/diag ----------
__global__ void k_smooth(const float* __restrict__ xin, float* __restrict__ xout,
                         const float* __restrict__ b, const float* __restrict__ Av,
                         const int* __restrict__ Acl) {
    int i = blockIdx.x * blockDim.x + threadIdx.x;
    if (i >= FN) return;
    float diag = __ldg(&Av[i * FD]);
    float s = 0.f;
#pragma unroll
    for (int j = 0; j < FD; j++)
        s += __ldg(&Av[i * FD + j]) * __ldg(&xin[__ldg(&Acl[i * FD + j])]);
    xout[i] = xin[i] + W_JAC * (b[i] - s) / diag;
}

// ---- residual + restriction: bc += P^T (b - A x); g_bc zero on entry -------
__global__ void k_resid_bc(const float* __restrict__ xin, const float* __restrict__ b,
                           const float* __restrict__ Av, const int* __restrict__ Acl,
                           const float* __restrict__ Pv, const int* __restrict__ Pc) {
    int i = blockIdx.x * blockDim.x + threadIdx.x;
    if (i >= FN) return;
    float s = 0.f;
#pragma unroll
    for (int j = 0; j < FD; j++)
        s += __ldg(&Av[i * FD + j]) * __ldg(&xin[__ldg(&Acl[i * FD + j])]);
    float r = b[i] - s;
#pragma unroll
    for (int k = 0; k < FK; k++)
        atomicAdd(&g_bc[__ldg(&Pc[i * FK + k])], __ldg(&Pv[i * FK + k]) * r);
}

// ---- cfirst: wdc = W/diag; xc0 = wdc*bc; patch accurate fp32 diag into Ach --
__global__ void k_cfirst(float* __restrict__ xc) {
    int c = blockIdx.x * blockDim.x + threadIdx.x;
    if (c >= FNC) return;
    float dc = g_dc[c];
    float w = W_JAC / dc;
    g_wdc[c] = w;
    xc[c] = g_bc[c] * w;
    g_Ach[(size_t)c * FNC + c] = __float2half_rn(dc);  // remove fp16 accum noise on diag
}

// ---- coarse Jacobi sweep: fp16 dense matvec, warp per row ------------------
// if last!=0 (final sweep of final cycle): after computing, each block zeroes
// the 8 Ach rows it owns (no other block reads them) and block 0 zeroes g_dc,
// restoring the accumulators for the next kernel_launch call.
__global__ void k_citer(const float* __restrict__ xin, float* __restrict__ xout,
                        int last) {
    int gw = (blockIdx.x * blockDim.x + threadIdx.x) >> 5;
    int lane = threadIdx.x & 31;
    const uint4* rowp = (const uint4*)(g_Ach + (size_t)gw * FNC); // 512 uint4/row
    const float4* xv = (const float4*)xin;
    float s = 0.f;
#pragma unroll 4
    for (int it = 0; it < 16; it++) {
        int idx = it * 32 + lane;
        uint4 a = rowp[idx];
        float4 xa = __ldg(xv + idx * 2);
        float4 xb = __ldg(xv + idx * 2 + 1);
        float2 f;
        f = __half22float2(*(__half2*)&a.x); s += f.x * xa.x + f.y * xa.y;
        f = __half22float2(*(__half2*)&a.y); s += f.x * xa.z + f.y * xa.w;
        f = __half22float2(*(__half2*)&a.z); s += f.x * xb.x + f.y * xb.y;
        f = __half22float2(*(__half2*)&a.w); s += f.x * xb.z + f.y * xb.w;
    }
#pragma unroll
    for (int o = 16; o; o >>= 1) s += __shfl_xor_sync(0xffffffffu, s, o);
    if (lane == 0)
        xout[gw] = __ldg(&xin[gw]) + g_wdc[gw] * (g_bc[gw] - s);

    if (last) {
        // zero this block's 8 rows of g_Ach: 8 rows * 4096 halves = 64 KB
        uint4 z = make_uint4(0u, 0u, 0u, 0u);
        uint4* slice = (uint4*)(g_Ach + (size_t)blockIdx.x * 8 * FNC);
        // 8*4096 halves = 4096 uint4; 256 threads -> 16 each
#pragma unroll
        for (int r = 0; r < 16; r++)
            slice[r * 256 + threadIdx.x] = z;
        if (blockIdx.x == 0) {
            float4* d4 = (float4*)g_dc;                 // 1024 float4
            float4 fz = make_float4(0.f, 0.f, 0.f, 0.f);
#pragma unroll
            for (int r = 0; r < 4; r++)
                d4[r * 256 + threadIdx.x] = fz;
        }
    }
}

// ---- prolongation / correction: xout = xin + P xc; also re-zero g_bc -------
__global__ void k_prolong(const float* __restrict__ xin, float* __restrict__ xout,
                          const float* __restrict__ Pv, const int* __restrict__ Pc,
                          const float* __restrict__ xc) {
    int i = blockIdx.x * blockDim.x + threadIdx.x;
    if (i >= FN) return;
    float s = 0.f;
#pragma unroll
    for (int k = 0; k < FK; k++)
        s += __ldg(&Pv[i * FK + k]) * __ldg(&xc[__ldg(&Pc[i * FK + k])]);
    xout[i] = xin[i] + s;
    if (i < FNC) g_bc[i] = 0.f;     // restore for next restriction / next call
}

// ---------------------------------------------------------------------------
extern "C" void kernel_launch(void* const* d_in, const int* in_sizes, int n_in,
                              void* d_out, int out_size) {
    const float* b   = (const float*)d_in[0];
    const float* x0  = (const float*)d_in[1];
    const float* Av  = (const float*)d_in[2];
    const float* Pv  = (const float*)d_in[3];
    const int*   Acl = (const int*)d_in[4];
    const int*   Pc  = (const int*)d_in[5];
    float* out = (float*)d_out;

    float *xbuf, *xcbase;
    cudaGetSymbolAddress((void**)&xbuf, g_xbuf);
    cudaGetSymbolAddress((void**)&xcbase, g_xc);
    float* bufs[2] = { xbuf, xbuf + FN };
    float* xc0 = xcbase;
    float* xc1 = xcbase + FNC;

    const int BT = 256;
    const int GB_N = (FN + BT - 1) / BT;             // 1024 blocks
    const int GB_NC = (FNC + BT - 1) / BT;           // 16 blocks
    const int GB_CITER = FNC * 32 / BT;              // 512 blocks, warp per row

    // RAP straight into fp16 (+ fp32 diag); accumulators arrive zeroed
    k_rap<<<(FN * FD + BT - 1) / BT, BT>>>(Av, Acl, Pv, Pc);

    const float* cur = x0;
    int nb = 0;
    for (int cyc = 0; cyc < 2; ++cyc) {
        for (int s = 0; s < 3; ++s) {
            k_smooth<<<GB_N, BT>>>(cur, bufs[nb], b, Av, Acl);
            cur = bufs[nb]; nb ^= 1;
        }
        k_resid_bc<<<GB_N, BT>>>(cur, b, Av, Acl, Pv, Pc);
        k_cfirst<<<GB_NC, BT>>>(xc0);
        float* ci = xc0; float* co = xc1;
        for (int t = 0; t < 9; ++t) {
            int last = (cyc == 1 && t == 8) ? 1 : 0;
            k_citer<<<GB_CITER, BT>>>(ci, co, last);
            float* tmp = ci; ci = co; co = tmp;
        }
        k_prolong<<<GB_N, BT>>>(cur, bufs[nb], Pv, Pc, ci);
        cur = bufs[nb]; nb ^= 1;
        for (int s = 0; s < 3; ++s) {
            float* dst = (cyc == 1 && s == 2) ? out : bufs[nb];
            k_smooth<<<GB_N, BT>>>(cur, dst, b, Av, Acl);
            cur = dst; nb ^= 1;
        }
    }
}

// round 14
// speedup vs baseline: 1.7985x; 1.7985x over previous
#include <cuda_runtime.h>
#include <cuda_fp16.h>

#define FN   262144
#define FNC  4096
#define FD   5
#define FK   4
#define W_JAC (2.0f/3.0f)

// ---- static device scratch -------------------------------------------------
__device__ float  g_Ac[FNC * FNC];     // fp32 RAP accumulator (re-zeroed by k_convert)
__device__ __half g_Ach[FNC * FNC];    // fp16 coarse operator for matvecs
__device__ float  g_wdc[FNC];          // W / diag(Ac)
__device__ float  g_bc[FNC];
__device__ float  g_xc[2 * FNC];
__device__ float  g_xbuf[2 * FN];

// ---- RAP: one thread per (row i, nz j); 16 fp32 atomics --------------------
__global__ void k_rap(const float* __restrict__ Av, const int* __restrict__ Acl,
                      const float* __restrict__ Pv, const int* __restrict__ Pc) {
    int t = blockIdx.x * blockDim.x + threadIdx.x;
    if (t >= FN * FD) return;
    int i = t / FD;
    int j = t - i * FD;
    int cj = __ldg(&Acl[i * FD + j]);
    float a = __ldg(&Av[i * FD + j]);
    float4 pa4 = __ldg((const float4*)(Pv + i * 4));
    int4   ia4 = __ldg((const int4*)(Pc + i * 4));
    float4 qb4 = __ldg((const float4*)(Pv + cj * 4));
    int4   ib4 = __ldg((const int4*)(Pc + cj * 4));
    float pa[FK] = {pa4.x * a, pa4.y * a, pa4.z * a, pa4.w * a};
    int   ia[FK] = {ia4.x, ia4.y, ia4.z, ia4.w};
    float qb[FK] = {qb4.x, qb4.y, qb4.z, qb4.w};
    int   ib[FK] = {ib4.x, ib4.y, ib4.z, ib4.w};
#pragma unroll
    for (int ka = 0; ka < FK; ka++) {
        int base = ia[ka] * FNC;
#pragma unroll
        for (int kb = 0; kb < FK; kb++)
            atomicAdd(&g_Ac[base + ib[kb]], pa[ka] * qb[kb]);
    }
}

// ---- convert fp32 Ac -> fp16 Ach, extract W/diag, re-zero fp32 Ac ----------
// (replaces zero_Ac + diagc kernels from R1)
__global__ void k_convert() {
    size_t base = (size_t)(blockIdx.x * blockDim.x + threadIdx.x) * 8;
    float4 a = *(const float4*)(g_Ac + base);
    float4 b = *(const float4*)(g_Ac + base + 4);
    __half2* h = (__half2*)(g_Ach + base);
    h[0] = __floats2half2_rn(a.x, a.y);
    h[1] = __floats2half2_rn(a.z, a.w);
    h[2] = __floats2half2_rn(b.x, b.y);
    h[3] = __floats2half2_rn(b.z, b.w);
    int r = (int)(base >> 12);                 // row = base / 4096
    size_t dpos = ((size_t)r << 12) + r;       // diagonal linear index of this row
    if (dpos >= base && dpos < base + 8) {
        int o = (int)(dpos - base);
        float dv = (o == 0) ? a.x : (o == 1) ? a.y : (o == 2) ? a.z : (o == 3) ? a.w
                 : (o == 4) ? b.x : (o == 5) ? b.y : (o == 6) ? b.z : b.w;
        g_wdc[r] = W_JAC / dv;
    }
    float4 z = make_float4(0.f, 0.f, 0.f, 0.f);
    *(float4*)(g_Ac + base) = z;
    *(float4*)(g_Ac + base + 4) = z;
}

// ---- fine smoother (R1 form): xout = xin + W*(b - A xin)/diag --------------
__global__ void k_smooth(const float* __restrict__ xin, float* __restrict__ xout,
                         const float* __restrict__ b, const float* __restrict__ Av,
                         const int* __restrict__ Acl) {
    int i = blockIdx.x * blockDim.x + threadIdx.x;
    if (i >= FN) return;
    float diag = __ldg(&Av[i * FD]);
    float s = 0.f;
#pragma unroll
    for (int j = 0; j < FD; j++)
        s += __ldg(&Av[i * FD + j]) * __ldg(&xin[__ldg(&Acl[i * FD + j])]);
    xout[i] = xin[i] + W_JAC * (b[i] - s) / diag;
}

// ---- residual + restriction: bc += P^T (b - A x) ---------------------------
__global__ void k_resid_bc(const float* __restrict__ xin, const float* __restrict__ b,
                           const float* __restrict__ Av, const int* __restrict__ Acl,
                           const float* __restrict__ Pv, const int* __restrict__ Pc) {
    int i = blockIdx.x * blockDim.x + threadIdx.x;
    if (i >= FN) return;
    float s = 0.f;
#pragma unroll
    for (int j = 0; j < FD; j++)
        s += __ldg(&Av[i * FD + j]) * __ldg(&xin[__ldg(&Acl[i * FD + j])]);
    float r = b[i] - s;
#pragma unroll
    for (int k = 0; k < FK; k++)
        atomicAdd(&g_bc[__ldg(&Pc[i * FK + k])], __ldg(&Pv[i * FK + k]) * r);
}

__global__ void k_zero_bc() {
    int c = blockIdx.x * blockDim.x + threadIdx.x;
    if (c < FNC) g_bc[c] = 0.f;
}

// First coarse Jacobi sweep from xc=0:  xc = W/diag * bc
__global__ void k_cfirst(float* __restrict__ xc) {
    int c = blockIdx.x * blockDim.x + threadIdx.x;
    if (c < FNC) xc[c] = g_bc[c] * g_wdc[c];
}

// ---- coarse Jacobi sweep: fp16 dense matvec, warp per row, no smem ---------
__global__ void k_citer(const float* __restrict__ xin, float* __restrict__ xout) {
    int gw = (blockIdx.x * blockDim.x + threadIdx.x) >> 5;
    int lane = threadIdx.x & 31;
    const uint4* rowp = (const uint4*)(g_Ach + (size_t)gw * FNC); // 512 uint4/row
    const float4* xv = (const float4*)xin;
    float s = 0.f;
#pragma unroll 4
    for (int it = 0; it < 16; it++) {
        int idx = it * 32 + lane;
        uint4 a = rowp[idx];
        float4 xa = __ldg(xv + idx * 2);
        float4 xb = __ldg(xv + idx * 2 + 1);
        float2 f;
        f = __half22float2(*(__half2*)&a.x); s += f.x * xa.x + f.y * xa.y;
        f = __half22float2(*(__half2*)&a.y); s += f.x * xa.z + f.y * xa.w;
        f = __half22float2(*(__half2*)&a.z); s += f.x * xb.x + f.y * xb.y;
        f = __half22float2(*(__half2*)&a.w); s += f.x * xb.z + f.y * xb.w;
    }
#pragma unroll
    for (int o = 16; o; o >>= 1) s += __shfl_xor_sync(0xffffffffu, s, o);
    if (lane == 0)
        xout[gw] = __ldg(&xin[gw]) + g_wdc[gw] * (g_bc[gw] - s);
}

// ---- prolongation / correction: xout = xin + P xc --------------------------
__global__ void k_prolong(const float* __restrict__ xin, float* __restrict__ xout,
                          const float* __restrict__ Pv, const int* __restrict__ Pc,
                          const float* __restrict__ xc) {
    int i = blockIdx.x * blockDim.x + threadIdx.x;
    if (i >= FN) return;
    float s = 0.f;
#pragma unroll
    for (int k = 0; k < FK; k++)
        s += __ldg(&Pv[i * FK + k]) * __ldg(&xc[__ldg(&Pc[i * FK + k])]);
    xout[i] = xin[i] + s;
}

// ---------------------------------------------------------------------------
extern "C" void kernel_launch(void* const* d_in, const int* in_sizes, int n_in,
                              void* d_out, int out_size) {
    const float* b   = (const float*)d_in[0];
    const float* x0  = (const float*)d_in[1];
    const float* Av  = (const float*)d_in[2];
    const float* Pv  = (const float*)d_in[3];
    const int*   Acl = (const int*)d_in[4];
    const int*   Pc  = (const int*)d_in[5];
    float* out = (float*)d_out;

    float *xbuf, *xcbase;
    cudaGetSymbolAddress((void**)&xbuf, g_xbuf);
    cudaGetSymbolAddress((void**)&xcbase, g_xc);
    float* bufs[2] = { xbuf, xbuf + FN };
    float* xc0 = xcbase;
    float* xc1 = xcbase + FNC;

    const int BT = 256;
    const int GB_N = (FN + BT - 1) / BT;             // 1024 blocks
    const int GB_NC = (FNC + BT - 1) / BT;           // 16 blocks
    const int GB_CITER = FNC * 32 / BT;              // 512 blocks, warp per row

    // Setup: RAP into fp32 (g_Ac arrives zeroed; k_convert re-zeroes it),
    // then convert to fp16 + extract W/diag.
    k_rap<<<(FN * FD + BT - 1) / BT, BT>>>(Av, Acl, Pv, Pc);
    k_convert<<<FNC * FNC / 8 / BT, BT>>>();

    const float* cur = x0;
    int nb = 0;
    for (int cyc = 0; cyc < 2; ++cyc) {
        for (int s = 0; s < 3; ++s) {
            k_smooth<<<GB_N, BT>>>(cur, bufs[nb], b, Av, Acl);
            cur = bufs[nb]; nb ^= 1;
        }
        k_zero_bc<<<GB_NC, BT>>>();
        k_resid_bc<<<GB_N, BT>>>(cur, b, Av, Acl, Pv, Pc);
        k_cfirst<<<GB_NC, BT>>>(xc0);
        float* ci = xc0; float* co = xc1;
        for (int t = 0; t < 9; ++t) {
            k_citer<<<GB_CITER, BT>>>(ci, co);
            float* tmp = ci; ci = co; co = tmp;
        }
        k_prolong<<<GB_N, BT>>>(cur, bufs[nb], Pv, Pc, ci);
        cur = bufs[nb]; nb ^= 1;
        for (int s = 0; s < 3; ++s) {
            float* dst = (cyc == 1 && s == 2) ? out : bufs[nb];
            k_smooth<<<GB_N, BT>>>(cur, dst, b, Av, Acl);
            cur = dst; nb ^= 1;
        }
    }
}

// round 17
// speedup vs baseline: 1.8470x; 1.0269x over previous
#include <cuda_runtime.h>
#include <cuda_fp16.h>

#define FN   262144
#define FNC  4096
#define FD   5
#define FK   4
#define W_JAC (2.0f/3.0f)

// ---- static device scratch (zero-init; kernels restore invariants) ---------
__device__ float  g_Ac[FNC * FNC];     // fp32 RAP accumulator; zero on entry,
                                       // re-zeroed by the LAST citer each call
__device__ __half g_Ach[FNC * FNC];    // fp16 coarse operator (written by citer #1)
__device__ float  g_wdc[FNC];          // W / diag(Ac)
__device__ float  g_bc[FNC];           // zero on entry; re-zeroed by prolong
__device__ float  g_xc[2 * FNC];
__device__ float  g_xbuf[2 * FN];

// ---- RAP: one thread per (row i, nz j); 16 fp32 atomics --------------------
__global__ void k_rap(const float* __restrict__ Av, const int* __restrict__ Acl,
                      const float* __restrict__ Pv, const int* __restrict__ Pc) {
    int t = blockIdx.x * blockDim.x + threadIdx.x;
    if (t >= FN * FD) return;
    int i = t / FD;
    int j = t - i * FD;
    int cj = __ldg(&Acl[i * FD + j]);
    float a = __ldg(&Av[i * FD + j]);
    float4 pa4 = __ldg((const float4*)(Pv + i * 4));
    int4   ia4 = __ldg((const int4*)(Pc + i * 4));
    float4 qb4 = __ldg((const float4*)(Pv + cj * 4));
    int4   ib4 = __ldg((const int4*)(Pc + cj * 4));
    float pa[FK] = {pa4.x * a, pa4.y * a, pa4.z * a, pa4.w * a};
    int   ia[FK] = {ia4.x, ia4.y, ia4.z, ia4.w};
    float qb[FK] = {qb4.x, qb4.y, qb4.z, qb4.w};
    int   ib[FK] = {ib4.x, ib4.y, ib4.z, ib4.w};
#pragma unroll
    for (int ka = 0; ka < FK; ka++) {
        int base = ia[ka] * FNC;
#pragma unroll
        for (int kb = 0; kb < FK; kb++)
            atomicAdd(&g_Ac[base + ib[kb]], pa[ka] * qb[kb]);
    }
}

// ---- diag extraction: g_wdc = W / diag(Ac) ---------------------------------
__global__ void k_diagc() {
    int c = blockIdx.x * blockDim.x + threadIdx.x;
    if (c < FNC) g_wdc[c] = W_JAC / g_Ac[(size_t)c * FNC + c];
}

// ---- fine smoother (R1 form) -----------------------------------------------
__global__ void k_smooth(const float* __restrict__ xin, float* __restrict__ xout,
                         const float* __restrict__ b, const float* __restrict__ Av,
                         const int* __restrict__ Acl) {
    int i = blockIdx.x * blockDim.x + threadIdx.x;
    if (i >= FN) return;
    float diag = __ldg(&Av[i * FD]);
    float s = 0.f;
#pragma unroll
    for (int j = 0; j < FD; j++)
        s += __ldg(&Av[i * FD + j]) * __ldg(&xin[__ldg(&Acl[i * FD + j])]);
    xout[i] = xin[i] + W_JAC * (b[i] - s) / diag;
}

// ---- residual + restriction: bc += P^T (b - A x); bc zero on entry ---------
__global__ void k_resid_bc(const float* __restrict__ xin, const float* __restrict__ b,
                           const float* __restrict__ Av, const int* __restrict__ Acl,
                           const float* __restrict__ Pv, const int* __restrict__ Pc) {
    int i = blockIdx.x * blockDim.x + threadIdx.x;
    if (i >= FN) return;
    float s = 0.f;
#pragma unroll
    for (int j = 0; j < FD; j++)
        s += __ldg(&Av[i * FD + j]) * __ldg(&xin[__ldg(&Acl[i * FD + j])]);
    float r = b[i] - s;
#pragma unroll
    for (int k = 0; k < FK; k++)
        atomicAdd(&g_bc[__ldg(&Pc[i * FK + k])], __ldg(&Pv[i * FK + k]) * r);
}

// ---- first coarse sweep from xc=0: xc = (W/diag) * bc ----------------------
__global__ void k_cfirst(float* __restrict__ xc) {
    int c = blockIdx.x * blockDim.x + threadIdx.x;
    if (c < FNC) xc[c] = g_bc[c] * g_wdc[c];
}

// ---- citer #1 of cycle 0: fp32 matvec, converts rows to fp16 on the fly ----
__global__ void k_citer_conv(const float* __restrict__ xin, float* __restrict__ xout) {
    int gw = (blockIdx.x * blockDim.x + threadIdx.x) >> 5;
    int lane = threadIdx.x & 31;
    const float4* row = (const float4*)(g_Ac + (size_t)gw * FNC);  // 1024 float4
    uint2* hrow = (uint2*)(g_Ach + (size_t)gw * FNC);              // 1024 uint2
    const float4* xv = (const float4*)xin;
    float s = 0.f;
#pragma unroll 4
    for (int j = lane; j < FNC / 4; j += 32) {
        float4 a = row[j];
        float4 x4 = __ldg(xv + j);
        s += a.x * x4.x + a.y * x4.y + a.z * x4.z + a.w * x4.w;
        __half2 h0 = __floats2half2_rn(a.x, a.y);
        __half2 h1 = __floats2half2_rn(a.z, a.w);
        hrow[j] = make_uint2(*(unsigned*)&h0, *(unsigned*)&h1);
    }
#pragma unroll
    for (int o = 16; o; o >>= 1) s += __shfl_xor_sync(0xffffffffu, s, o);
    if (lane == 0)
        xout[gw] = __ldg(&xin[gw]) + g_wdc[gw] * (g_bc[gw] - s);
}

// ---- coarse Jacobi sweep: fp16 dense matvec, warp per row ------------------
// last!=0 (final sweep of final cycle): each block additionally re-zeroes the
// 8 fp32 Ac rows it owns, restoring the accumulator for the next call.
__global__ void k_citer(const float* __restrict__ xin, float* __restrict__ xout,
                        int last) {
    int gw = (blockIdx.x * blockDim.x + threadIdx.x) >> 5;
    int lane = threadIdx.x & 31;
    const uint4* rowp = (const uint4*)(g_Ach + (size_t)gw * FNC); // 512 uint4/row
    const float4* xv = (const float4*)xin;
    float s = 0.f;
#pragma unroll 4
    for (int it = 0; it < 16; it++) {
        int idx = it * 32 + lane;
        uint4 a = rowp[idx];
        float4 xa = __ldg(xv + idx * 2);
        float4 xb = __ldg(xv + idx * 2 + 1);
        float2 f;
        f = __half22float2(*(__half2*)&a.x); s += f.x * xa.x + f.y * xa.y;
        f = __half22float2(*(__half2*)&a.y); s += f.x * xa.z + f.y * xa.w;
        f = __half22float2(*(__half2*)&a.z); s += f.x * xb.x + f.y * xb.y;
        f = __half22float2(*(__half2*)&a.w); s += f.x * xb.z + f.y * xb.w;
    }
#pragma unroll
    for (int o = 16; o; o >>= 1) s += __shfl_xor_sync(0xffffffffu, s, o);
    if (lane == 0)
        xout[gw] = __ldg(&xin[gw]) + g_wdc[gw] * (g_bc[gw] - s);

    if (last) {
        // zero this block's 8 fp32 rows: 8*4096 floats = 8192 float4; 32/thread
        float4 z = make_float4(0.f, 0.f, 0.f, 0.f);
        float4* slice = (float4*)(g_Ac + (size_t)blockIdx.x * 8 * FNC);
#pragma unroll
        for (int r = 0; r < 32; r++)
            slice[r * 256 + threadIdx.x] = z;
    }
}

// ---- prolongation / correction; also re-zeroes g_bc for next use -----------
__global__ void k_prolong(const float* __restrict__ xin, float* __restrict__ xout,
                          const float* __restrict__ Pv, const int* __restrict__ Pc,
                          const float* __restrict__ xc) {
    int i = blockIdx.x * blockDim.x + threadIdx.x;
    if (i >= FN) return;
    float s = 0.f;
#pragma unroll
    for (int k = 0; k < FK; k++)
        s += __ldg(&Pv[i * FK + k]) * __ldg(&xc[__ldg(&Pc[i * FK + k])]);
    xout[i] = xin[i] + s;
    if (i < FNC) g_bc[i] = 0.f;
}

// ---------------------------------------------------------------------------
extern "C" void kernel_launch(void* const* d_in, const int* in_sizes, int n_in,
                              void* d_out, int out_size) {
    const float* b   = (const float*)d_in[0];
    const float* x0  = (const float*)d_in[1];
    const float* Av  = (const float*)d_in[2];
    const float* Pv  = (const float*)d_in[3];
    const int*   Acl = (const int*)d_in[4];
    const int*   Pc  = (const int*)d_in[5];
    float* out = (float*)d_out;

    float *xbuf, *xcbase;
    cudaGetSymbolAddress((void**)&xbuf, g_xbuf);
    cudaGetSymbolAddress((void**)&xcbase, g_xc);
    float* bufs[2] = { xbuf, xbuf + FN };
    float* xc0 = xcbase;
    float* xc1 = xcbase + FNC;

    const int BT = 256;
    const int GB_N = (FN + BT - 1) / BT;             // 1024 blocks
    const int GB_NC = (FNC + BT - 1) / BT;           // 16 blocks
    const int GB_CITER = FNC * 32 / BT;              // 512 blocks, warp per row

    // RAP into fp32 (accumulator arrives zeroed), extract W/diag
    k_rap<<<(FN * FD + BT - 1) / BT, BT>>>(Av, Acl, Pv, Pc);
    k_diagc<<<GB_NC, BT>>>();

    const float* cur = x0;
    int nb = 0;
    for (int cyc = 0; cyc < 2; ++cyc) {
        for (int s = 0; s < 3; ++s) {
            k_smooth<<<GB_N, BT>>>(cur, bufs[nb], b, Av, Acl);
            cur = bufs[nb]; nb ^= 1;
        }
        k_resid_bc<<<GB_N, BT>>>(cur, b, Av, Acl, Pv, Pc);   // bc was zero
        k_cfirst<<<GB_NC, BT>>>(xc0);
        float* ci = xc0; float* co = xc1;
        for (int t = 0; t < 9; ++t) {
            if (cyc == 0 && t == 0) {
                // fp32 matvec + on-the-fly fp16 conversion of Ac
                k_citer_conv<<<GB_CITER, BT>>>(ci, co);
            } else {
                int last = (cyc == 1 && t == 8) ? 1 : 0;
                k_citer<<<GB_CITER, BT>>>(ci, co, last);
            }
            float* tmp = ci; ci = co; co = tmp;
        }
        k_prolong<<<GB_N, BT>>>(cur, bufs[nb], Pv, Pc, ci);  // also zeroes bc
        cur = bufs[nb]; nb ^= 1;
        for (int s = 0; s < 3; ++s) {
            float* dst = (cyc == 1 && s == 2) ? out : bufs[nb];
            k_smooth<<<GB_N, BT>>>(cur, dst, b, Av, Acl);
            cur = dst; nb ^= 1;
        }
    }
}